// round 11
// baseline (speedup 1.0000x reference)
#include <cuda_runtime.h>
#include <cuda_fp16.h>
#include <cstdint>

#define N_D 2000
#define E_D 32000
#define N_E 50000
#define E_E 800000
#define IN_F 128
#define DHC 64
#define EHC 64
#define OUTC 32
#define HEADS 4

// ------------------------- scratch (device globals) -------------------------
__device__ __half g_d_h1h[N_D * HEADS * DHC];
__device__ float  g_d_as1[N_D * HEADS];
__device__ float  g_d_ad1[N_D * HEADS];
__device__ float  g_d_out1[N_D * HEADS * DHC];
__device__ float  g_d_h2 [N_D * DHC];
__device__ float  g_d_as2[N_D];
__device__ float  g_d_ad2[N_D];
__device__ float  g_d_out2[N_D * DHC];
__device__ float  g_dproj [N_D * HEADS * EHC];

__device__ __half g_e_h1h[N_E * HEADS * EHC];
__device__ float  g_e_as1[N_E * HEADS];
__device__ float  g_e_ad1[N_E * HEADS];
__device__ __half g_e_out1h[N_E * HEADS * EHC];
__device__ __half g_e_h2h[N_E * OUTC];
__device__ float  g_e_as2[N_E];
__device__ float  g_e_ad2[N_E];

// alpha-precompute scratch
__device__ float g_u_src[IN_F * HEADS];
__device__ float g_u_dst[IN_F * HEADS];
__device__ float g_v_src[N_D * HEADS];
__device__ float g_v_dst[N_D * HEADS];

// per-edge alpha spill (4 heads)
__device__ float4 g_ealpha[E_E + N_E];

// CSR scratch
__device__ int g_deg_d [N_D];
__device__ int g_cur_d [N_D];
__device__ int g_row_d [N_D + 1];
__device__ int g_colv_d[E_D + N_D];
__device__ int g_degcur_e[2 * N_E];
__device__ int g_row_e [N_E + 1];
__device__ int g_colv_e[E_E + N_E];
__device__ int g_bs_e  [256];

static inline int cdiv(int a, int b) { return (a + b - 1) / b; }

__device__ __forceinline__ float to_f(float x)  { return x; }
__device__ __forceinline__ float to_f(__half x) { return __half2float(x); }

// ================== dept CSR: single-block build ============================
__global__ void build_csr_small(const int* __restrict__ ei, int E, int N,
                                int* __restrict__ deg, int* __restrict__ cur,
                                int* __restrict__ rowptr, int* __restrict__ colv) {
    __shared__ int sh[1024];
    __shared__ int carry;
    int tid = threadIdx.x;
    for (int i = tid; i < N; i += 1024) { deg[i] = 0; cur[i] = 0; }
    __syncthreads();
    for (int i = tid; i < E; i += 1024) atomicAdd(&deg[ei[E + i]], 1);
    if (tid == 0) carry = 0;
    __syncthreads();
    for (int base = 0; base < N; base += 1024) {
        int v = (base + tid < N) ? (deg[base + tid] + 1) : 0;
        sh[tid] = v;
        __syncthreads();
        for (int off = 1; off < 1024; off <<= 1) {
            int x = (tid >= off) ? sh[tid - off] : 0;
            __syncthreads();
            sh[tid] += x;
            __syncthreads();
        }
        if (base + tid < N) rowptr[base + tid] = carry + sh[tid] - v;
        __syncthreads();
        if (tid == 0) carry += sh[1023];
        __syncthreads();
    }
    if (tid == 0) rowptr[N] = carry;
    __syncthreads();
    for (int i = tid; i < E + N; i += 1024) {
        int s, d;
        if (i < E) { s = ei[i]; d = ei[E + i]; }
        else       { s = d = i - E; }
        colv[rowptr[d] + atomicAdd(&cur[d], 1)] = s;
    }
}

// =============================== emp CSR build ===============================
__global__ void deg_count(const int* __restrict__ ei, int E, int* __restrict__ deg) {
    int t = blockIdx.x * blockDim.x + threadIdx.x;
    if (t < E) atomicAdd(&deg[ei[E + t]], 1);
}

__global__ void block_sum(const int* __restrict__ deg, int N, int* __restrict__ bsum) {
    __shared__ int sh[256];
    int i = blockIdx.x * 256 + threadIdx.x;
    sh[threadIdx.x] = (i < N) ? (deg[i] + 1) : 0;
    __syncthreads();
    for (int off = 128; off; off >>= 1) {
        if (threadIdx.x < off) sh[threadIdx.x] += sh[threadIdx.x + off];
        __syncthreads();
    }
    if (threadIdx.x == 0) bsum[blockIdx.x] = sh[0];
}

__global__ void scan_bsums(int* __restrict__ bsum, int nb, int* __restrict__ rowptr,
                           int total, int N) {
    if (threadIdx.x == 0) {
        int acc = 0;
        for (int i = 0; i < nb; i++) { int v = bsum[i]; bsum[i] = acc; acc += v; }
        rowptr[N] = total;
    }
}

__global__ void scan_final(const int* __restrict__ deg, const int* __restrict__ bsum,
                           int N, int* __restrict__ rowptr) {
    __shared__ int sh[256];
    int i = blockIdx.x * 256 + threadIdx.x;
    int v = (i < N) ? (deg[i] + 1) : 0;
    sh[threadIdx.x] = v;
    __syncthreads();
    for (int off = 1; off < 256; off <<= 1) {
        int x = (threadIdx.x >= off) ? sh[threadIdx.x - off] : 0;
        __syncthreads();
        sh[threadIdx.x] += x;
        __syncthreads();
    }
    if (i < N) rowptr[i] = bsum[blockIdx.x] + sh[threadIdx.x] - v;
}

__global__ void fill_csr(const int* __restrict__ ei, int E, int N,
                         const int* __restrict__ rowptr, int* __restrict__ cur,
                         int* __restrict__ colv) {
    int t = blockIdx.x * blockDim.x + threadIdx.x;
    if (t >= E + N) return;
    int src, dst;
    if (t < E) { src = ei[t]; dst = ei[E + t]; }
    else       { src = dst = t - E; }
    int pos = rowptr[dst] + atomicAdd(&cur[dst], 1);
    colv[pos] = src;
}

// ======================= MMA helpers ========================================
__device__ __forceinline__ uint32_t f2tf32(float x) {
    uint32_t r;
    asm("cvt.rna.tf32.f32 %0, %1;" : "=r"(r) : "f"(x));
    return r;
}

__device__ __forceinline__ void mma_tf32(float (&d)[4], const uint32_t* a, const uint32_t* b) {
    asm volatile(
        "mma.sync.aligned.m16n8k8.row.col.f32.tf32.tf32.f32 "
        "{%0,%1,%2,%3}, {%4,%5,%6,%7}, {%8,%9}, {%0,%1,%2,%3};"
        : "+f"(d[0]), "+f"(d[1]), "+f"(d[2]), "+f"(d[3])
        : "r"(a[0]), "r"(a[1]), "r"(a[2]), "r"(a[3]), "r"(b[0]), "r"(b[1]));
}

__device__ __forceinline__ void mma_f16(float (&d)[4], const uint32_t* a, const uint32_t* b) {
    asm volatile(
        "mma.sync.aligned.m16n8k16.row.col.f32.f16.f16.f32 "
        "{%0,%1,%2,%3}, {%4,%5,%6,%7}, {%8,%9}, {%0,%1,%2,%3};"
        : "+f"(d[0]), "+f"(d[1]), "+f"(d[2]), "+f"(d[3])
        : "r"(a[0]), "r"(a[1]), "r"(a[2]), "r"(a[3]), "r"(b[0]), "r"(b[1]));
}

#define AS_STRIDE 20
#define BS_STRIDE 136

// =================== tf32 GEMM (kept for dproj, fp32 out) ====================
template<typename OutT>
__global__ __launch_bounds__(256) void gemm_tc(
        const float* __restrict__ A, const float* __restrict__ B,
        OutT* __restrict__ C, int M, int N, int K,
        const float* __restrict__ add, const int* __restrict__ idx) {
    __shared__ uint32_t As[128 * AS_STRIDE];
    __shared__ uint32_t Bs[16 * BS_STRIDE];

    const int t = threadIdx.x;
    const int lane = t & 31;
    const int warp = t >> 5;
    const int warpM = warp & 1;
    const int warpN = warp >> 1;
    const int g  = lane >> 2;
    const int tq = lane & 3;
    const int rowbase = blockIdx.y * 128;
    const int colbase = blockIdx.x * 128;

    const int am = t >> 1;
    const int ak = (t & 1) * 8;
    const int bk = t >> 4;
    const int bn = (t & 15) * 8;

    float acc[4][4][4] = {};
    float av[8], bv[8];

    {
        float4 z = make_float4(0.f, 0.f, 0.f, 0.f);
        float4 v0 = z, v1 = z;
        if (rowbase + am < M) {
            v0 = *(const float4*)&A[(size_t)(rowbase + am) * K + ak];
            v1 = *(const float4*)&A[(size_t)(rowbase + am) * K + ak + 4];
        }
        av[0]=v0.x; av[1]=v0.y; av[2]=v0.z; av[3]=v0.w;
        av[4]=v1.x; av[5]=v1.y; av[6]=v1.z; av[7]=v1.w;
        float4 w0 = *(const float4*)&B[(size_t)bk * N + colbase + bn];
        float4 w1 = *(const float4*)&B[(size_t)bk * N + colbase + bn + 4];
        bv[0]=w0.x; bv[1]=w0.y; bv[2]=w0.z; bv[3]=w0.w;
        bv[4]=w1.x; bv[5]=w1.y; bv[6]=w1.z; bv[7]=w1.w;
    }

    for (int k0 = 0; k0 < K; k0 += 16) {
#pragma unroll
        for (int i = 0; i < 8; i++) As[am * AS_STRIDE + ak + i] = f2tf32(av[i]);
#pragma unroll
        for (int i = 0; i < 8; i++) Bs[bk * BS_STRIDE + bn + i] = f2tf32(bv[i]);
        __syncthreads();

        if (k0 + 16 < K) {
            const int kn = k0 + 16;
            float4 z = make_float4(0.f, 0.f, 0.f, 0.f);
            float4 v0 = z, v1 = z;
            if (rowbase + am < M) {
                v0 = *(const float4*)&A[(size_t)(rowbase + am) * K + kn + ak];
                v1 = *(const float4*)&A[(size_t)(rowbase + am) * K + kn + ak + 4];
            }
            av[0]=v0.x; av[1]=v0.y; av[2]=v0.z; av[3]=v0.w;
            av[4]=v1.x; av[5]=v1.y; av[6]=v1.z; av[7]=v1.w;
            float4 w0 = *(const float4*)&B[(size_t)(kn + bk) * N + colbase + bn];
            float4 w1 = *(const float4*)&B[(size_t)(kn + bk) * N + colbase + bn + 4];
            bv[0]=w0.x; bv[1]=w0.y; bv[2]=w0.z; bv[3]=w0.w;
            bv[4]=w1.x; bv[5]=w1.y; bv[6]=w1.z; bv[7]=w1.w;
        }

#pragma unroll
        for (int s = 0; s < 2; s++) {
            uint32_t ah[4][4], bh[4][2];
#pragma unroll
            for (int mi = 0; mi < 4; mi++) {
                int r0 = (warpM * 64 + mi * 16 + g) * AS_STRIDE;
                int r1 = r0 + 8 * AS_STRIDE;
                int c0 = s * 8 + tq;
                ah[mi][0] = As[r0 + c0];     ah[mi][1] = As[r1 + c0];
                ah[mi][2] = As[r0 + c0 + 4]; ah[mi][3] = As[r1 + c0 + 4];
            }
#pragma unroll
            for (int ni = 0; ni < 4; ni++) {
                int bc = warpN * 32 + ni * 8 + g;
                int kr0 = (s * 8 + tq) * BS_STRIDE;
                int kr1 = (s * 8 + tq + 4) * BS_STRIDE;
                bh[ni][0] = Bs[kr0 + bc]; bh[ni][1] = Bs[kr1 + bc];
            }
#pragma unroll
            for (int mi = 0; mi < 4; mi++)
#pragma unroll
                for (int ni = 0; ni < 4; ni++)
                    mma_tf32(acc[mi][ni], ah[mi], bh[ni]);
        }
        __syncthreads();
    }

#pragma unroll
    for (int mi = 0; mi < 4; mi++) {
        int row0 = rowbase + warpM * 64 + mi * 16 + g;
        int row1 = row0 + 8;
        const float* ap0 = nullptr;
        const float* ap1 = nullptr;
        if (idx) {
            if (row0 < M) ap0 = add + (size_t)idx[row0] * N;
            if (row1 < M) ap1 = add + (size_t)idx[row1] * N;
        }
#pragma unroll
        for (int ni = 0; ni < 4; ni++) {
            int col = colbase + warpN * 32 + ni * 8 + 2 * tq;
            if (row0 < M) {
                float vx = acc[mi][ni][0], vy = acc[mi][ni][1];
                if (ap0) { vx += ap0[col]; vy += ap0[col + 1]; }
                if constexpr (sizeof(OutT) == 2) {
                    *(__half2*)&C[(size_t)row0 * N + col] = __floats2half2_rn(vx, vy);
                } else {
                    *(float2*)&C[(size_t)row0 * N + col] = make_float2(vx, vy);
                }
            }
            if (row1 < M) {
                float vx = acc[mi][ni][2], vy = acc[mi][ni][3];
                if (ap1) { vx += ap1[col]; vy += ap1[col + 1]; }
                if constexpr (sizeof(OutT) == 2) {
                    *(__half2*)&C[(size_t)row1 * N + col] = __floats2half2_rn(vx, vy);
                } else {
                    *(float2*)&C[(size_t)row1 * N + col] = make_float2(vx, vy);
                }
            }
        }
    }
}

// ============ fp16 HMMA GEMM 128x128 (fp32 in, cvt in-tile) =================
// C[M,N] = A@B (+ optional gathered fp32 row add). N%128==0, K%16==0.
#define AF_STRIDE 24
#define BF_STRIDE 24
template<typename OutT>
__global__ __launch_bounds__(256) void gemm_f16(
        const float* __restrict__ A, const float* __restrict__ B,
        OutT* __restrict__ C, int M, int N, int K,
        const float* __restrict__ add, const int* __restrict__ idx) {
    __shared__ __half As[128 * AF_STRIDE];    // [row][16] pad 24
    __shared__ __half Bst[128 * BF_STRIDE];   // [col][16] pad 24 (B transposed)

    const int t = threadIdx.x;
    const int lane = t & 31;
    const int warp = t >> 5;
    const int warpM = warp & 1;      // 64-row halves
    const int warpN = warp >> 1;     // 32-col quarters
    const int g  = lane >> 2;
    const int tq = lane & 3;
    const int rowbase = blockIdx.y * 128;
    const int colbase = blockIdx.x * 128;

    const int am = t >> 1;           // 0..127
    const int ak = (t & 1) * 8;      // 0 or 8
    const int bk = t >> 4;           // 0..15
    const int bn = (t & 15) * 8;     // 0..120

    float acc[4][4][4] = {};
    float av[8], bv[8];

    {
        float4 z = make_float4(0.f, 0.f, 0.f, 0.f);
        float4 v0 = z, v1 = z;
        if (rowbase + am < M) {
            v0 = *(const float4*)&A[(size_t)(rowbase + am) * K + ak];
            v1 = *(const float4*)&A[(size_t)(rowbase + am) * K + ak + 4];
        }
        av[0]=v0.x; av[1]=v0.y; av[2]=v0.z; av[3]=v0.w;
        av[4]=v1.x; av[5]=v1.y; av[6]=v1.z; av[7]=v1.w;
        float4 w0 = *(const float4*)&B[(size_t)bk * N + colbase + bn];
        float4 w1 = *(const float4*)&B[(size_t)bk * N + colbase + bn + 4];
        bv[0]=w0.x; bv[1]=w0.y; bv[2]=w0.z; bv[3]=w0.w;
        bv[4]=w1.x; bv[5]=w1.y; bv[6]=w1.z; bv[7]=w1.w;
    }

    for (int k0 = 0; k0 < K; k0 += 16) {
        {
            __half2 p[4];
#pragma unroll
            for (int i = 0; i < 4; i++) p[i] = __floats2half2_rn(av[2 * i], av[2 * i + 1]);
            *(uint4*)&As[am * AF_STRIDE + ak] = *(const uint4*)p;
        }
#pragma unroll
        for (int i = 0; i < 8; i++)
            Bst[(bn + i) * BF_STRIDE + bk] = __float2half_rn(bv[i]);
        __syncthreads();

        if (k0 + 16 < K) {
            const int kn = k0 + 16;
            float4 z = make_float4(0.f, 0.f, 0.f, 0.f);
            float4 v0 = z, v1 = z;
            if (rowbase + am < M) {
                v0 = *(const float4*)&A[(size_t)(rowbase + am) * K + kn + ak];
                v1 = *(const float4*)&A[(size_t)(rowbase + am) * K + kn + ak + 4];
            }
            av[0]=v0.x; av[1]=v0.y; av[2]=v0.z; av[3]=v0.w;
            av[4]=v1.x; av[5]=v1.y; av[6]=v1.z; av[7]=v1.w;
            float4 w0 = *(const float4*)&B[(size_t)(kn + bk) * N + colbase + bn];
            float4 w1 = *(const float4*)&B[(size_t)(kn + bk) * N + colbase + bn + 4];
            bv[0]=w0.x; bv[1]=w0.y; bv[2]=w0.z; bv[3]=w0.w;
            bv[4]=w1.x; bv[5]=w1.y; bv[6]=w1.z; bv[7]=w1.w;
        }

        uint32_t ar[4][4], br[4][2];
#pragma unroll
        for (int mi = 0; mi < 4; mi++) {
            int r0 = (warpM * 64 + mi * 16 + g) * AF_STRIDE;
            int r1 = r0 + 8 * AF_STRIDE;
            ar[mi][0] = *(const uint32_t*)&As[r0 + 2 * tq];
            ar[mi][1] = *(const uint32_t*)&As[r1 + 2 * tq];
            ar[mi][2] = *(const uint32_t*)&As[r0 + 2 * tq + 8];
            ar[mi][3] = *(const uint32_t*)&As[r1 + 2 * tq + 8];
        }
#pragma unroll
        for (int ni = 0; ni < 4; ni++) {
            int cb = (warpN * 32 + ni * 8 + g) * BF_STRIDE;
            br[ni][0] = *(const uint32_t*)&Bst[cb + 2 * tq];
            br[ni][1] = *(const uint32_t*)&Bst[cb + 2 * tq + 8];
        }
#pragma unroll
        for (int mi = 0; mi < 4; mi++)
#pragma unroll
            for (int ni = 0; ni < 4; ni++)
                mma_f16(acc[mi][ni], ar[mi], br[ni]);
        __syncthreads();
    }

#pragma unroll
    for (int mi = 0; mi < 4; mi++) {
        int row0 = rowbase + warpM * 64 + mi * 16 + g;
        int row1 = row0 + 8;
        const float* ap0 = nullptr;
        const float* ap1 = nullptr;
        if (idx) {
            if (row0 < M) ap0 = add + (size_t)idx[row0] * N;
            if (row1 < M) ap1 = add + (size_t)idx[row1] * N;
        }
#pragma unroll
        for (int ni = 0; ni < 4; ni++) {
            int col = colbase + warpN * 32 + ni * 8 + 2 * tq;
            if (row0 < M) {
                float vx = acc[mi][ni][0], vy = acc[mi][ni][1];
                if (ap0) { vx += ap0[col]; vy += ap0[col + 1]; }
                if constexpr (sizeof(OutT) == 2) {
                    *(__half2*)&C[(size_t)row0 * N + col] = __floats2half2_rn(vx, vy);
                } else {
                    *(float2*)&C[(size_t)row0 * N + col] = make_float2(vx, vy);
                }
            }
            if (row1 < M) {
                float vx = acc[mi][ni][2], vy = acc[mi][ni][3];
                if (ap1) { vx += ap1[col]; vy += ap1[col + 1]; }
                if constexpr (sizeof(OutT) == 2) {
                    *(__half2*)&C[(size_t)row1 * N + col] = __floats2half2_rn(vx, vy);
                } else {
                    *(float2*)&C[(size_t)row1 * N + col] = make_float2(vx, vy);
                }
            }
        }
    }
}

// ============ fp16 HMMA GEMM, N=32, A fp16, fused alpha-dot epilogue ========
#define AH_STRIDE 24
#define BH_STRIDE 24
__global__ __launch_bounds__(256) void gemm_n32_h(
        const __half* __restrict__ A, const float* __restrict__ B,
        __half* __restrict__ C, int M, int K,
        const float* __restrict__ a_src, const float* __restrict__ a_dst,
        float* __restrict__ as_out, float* __restrict__ ad_out) {
    __shared__ __half As_h[128 * AH_STRIDE];
    __shared__ __half Bst[32 * BH_STRIDE];
    __shared__ float sa[32], sd[32];

    const int t = threadIdx.x;
    const int lane = t & 31;
    const int warp = t >> 5;
    const int g  = lane >> 2;
    const int tq = lane & 3;
    const int rowbase = blockIdx.x * 128;

    const int am = t >> 1;
    const int ah_off = (t & 1) * 8;
    const int bk = t >> 4;
    const int bc = (t & 15) * 2;

    if (t < 32) { sa[t] = a_src[t]; sd[t] = a_dst[t]; }

    float acc[4][4] = {};
    uint4  a_pre = make_uint4(0, 0, 0, 0);
    float2 b_pre;

    if (rowbase + am < M)
        a_pre = *(const uint4*)&A[(size_t)(rowbase + am) * K + ah_off];
    b_pre = *(const float2*)&B[(size_t)bk * 32 + bc];

    for (int k0 = 0; k0 < K; k0 += 16) {
        *(uint4*)&As_h[am * AH_STRIDE + ah_off] = a_pre;
        Bst[(bc + 0) * BH_STRIDE + bk] = __float2half_rn(b_pre.x);
        Bst[(bc + 1) * BH_STRIDE + bk] = __float2half_rn(b_pre.y);
        __syncthreads();

        if (k0 + 16 < K) {
            a_pre = make_uint4(0, 0, 0, 0);
            if (rowbase + am < M)
                a_pre = *(const uint4*)&A[(size_t)(rowbase + am) * K + k0 + 16 + ah_off];
            b_pre = *(const float2*)&B[(size_t)(k0 + 16 + bk) * 32 + bc];
        }

        uint32_t ar[4];
        int r0 = (warp * 16 + g) * AH_STRIDE;
        int r1 = r0 + 8 * AH_STRIDE;
        ar[0] = *(const uint32_t*)&As_h[r0 + 2 * tq];
        ar[1] = *(const uint32_t*)&As_h[r1 + 2 * tq];
        ar[2] = *(const uint32_t*)&As_h[r0 + 2 * tq + 8];
        ar[3] = *(const uint32_t*)&As_h[r1 + 2 * tq + 8];
#pragma unroll
        for (int ni = 0; ni < 4; ni++) {
            uint32_t br[2];
            int cb = (ni * 8 + g) * BH_STRIDE;
            br[0] = *(const uint32_t*)&Bst[cb + 2 * tq];
            br[1] = *(const uint32_t*)&Bst[cb + 2 * tq + 8];
            mma_f16(acc[ni], ar, br);
        }
        __syncthreads();
    }

    int row0 = rowbase + warp * 16 + g;
    int row1 = row0 + 8;
    float s0 = 0.f, s1 = 0.f, d0 = 0.f, d1 = 0.f;
#pragma unroll
    for (int ni = 0; ni < 4; ni++) {
        int c0 = ni * 8 + 2 * tq;
        float a0 = sa[c0], a1 = sa[c0 + 1];
        float b0 = sd[c0], b1 = sd[c0 + 1];
        s0 += acc[ni][0] * a0 + acc[ni][1] * a1;
        s1 += acc[ni][2] * a0 + acc[ni][3] * a1;
        d0 += acc[ni][0] * b0 + acc[ni][1] * b1;
        d1 += acc[ni][2] * b0 + acc[ni][3] * b1;
        if (row0 < M) *(__half2*)&C[(size_t)row0 * 32 + c0] = __floats2half2_rn(acc[ni][0], acc[ni][1]);
        if (row1 < M) *(__half2*)&C[(size_t)row1 * 32 + c0] = __floats2half2_rn(acc[ni][2], acc[ni][3]);
    }
#pragma unroll
    for (int off = 1; off <= 2; off <<= 1) {
        s0 += __shfl_xor_sync(0xffffffffu, s0, off);
        s1 += __shfl_xor_sync(0xffffffffu, s1, off);
        d0 += __shfl_xor_sync(0xffffffffu, d0, off);
        d1 += __shfl_xor_sync(0xffffffffu, d1, off);
    }
    if (tq == 0) {
        if (row0 < M) { as_out[row0] = s0; ad_out[row0] = d0; }
        if (row1 < M) { as_out[row1] = s1; ad_out[row1] = d1; }
    }
}

// ============ GEMM 64x64x16 (dept2) with fused alpha-dot epilogue ===========
__global__ void gemm64a(const float* __restrict__ A, const float* __restrict__ B,
                        float* __restrict__ C, int M, int N, int K,
                        const float* __restrict__ a_src, const float* __restrict__ a_dst,
                        float* __restrict__ as_out, float* __restrict__ ad_out) {
    __shared__ float As[16][64];
    __shared__ float Bs[16][64];
    __shared__ float sa[64], sd[64];
    const int t  = threadIdx.x;
    const int tx = t & 15;
    const int ty = t >> 4;
    const int rowbase = blockIdx.y * 64;
    const int ar = t >> 2;
    const int ak = (t & 3) * 4;
    const int bk = t >> 4;
    const int bc = (t & 15) * 4;

    if (t < 64) { sa[t] = a_src[t]; sd[t] = a_dst[t]; }

    float acc[4][4] = {};
    for (int k0 = 0; k0 < K; k0 += 16) {
        float4 av = make_float4(0.f, 0.f, 0.f, 0.f);
        if (rowbase + ar < M)
            av = *(const float4*)&A[(size_t)(rowbase + ar) * K + k0 + ak];
        As[ak + 0][ar] = av.x; As[ak + 1][ar] = av.y;
        As[ak + 2][ar] = av.z; As[ak + 3][ar] = av.w;
        float4 bv = *(const float4*)&B[(size_t)(k0 + bk) * N + bc];
        *(float4*)&Bs[bk][bc] = bv;
        __syncthreads();
#pragma unroll
        for (int kk = 0; kk < 16; kk++) {
            float4 a = *(const float4*)&As[kk][ty * 4];
            float4 b = *(const float4*)&Bs[kk][tx * 4];
            acc[0][0] += a.x * b.x; acc[0][1] += a.x * b.y; acc[0][2] += a.x * b.z; acc[0][3] += a.x * b.w;
            acc[1][0] += a.y * b.x; acc[1][1] += a.y * b.y; acc[1][2] += a.y * b.z; acc[1][3] += a.y * b.w;
            acc[2][0] += a.z * b.x; acc[2][1] += a.z * b.y; acc[2][2] += a.z * b.z; acc[2][3] += a.z * b.w;
            acc[3][0] += a.w * b.x; acc[3][1] += a.w * b.y; acc[3][2] += a.w * b.z; acc[3][3] += a.w * b.w;
        }
        __syncthreads();
    }
#pragma unroll
    for (int i = 0; i < 4; i++) {
        int row = rowbase + ty * 4 + i;
        float ps = 0.f, pd = 0.f;
#pragma unroll
        for (int j = 0; j < 4; j++) {
            int col = tx * 4 + j;
            ps += acc[i][j] * sa[col];
            pd += acc[i][j] * sd[col];
        }
#pragma unroll
        for (int off = 1; off <= 8; off <<= 1) {
            ps += __shfl_xor_sync(0xffffffffu, ps, off);
            pd += __shfl_xor_sync(0xffffffffu, pd, off);
        }
        if (row < M) {
            *(float4*)&C[(size_t)row * N + tx * 4] =
                make_float4(acc[i][0], acc[i][1], acc[i][2], acc[i][3]);
            if (tx == 0) { as_out[row] = ps; ad_out[row] = pd; }
        }
    }
}

// -------------------- alpha precompute ----------------------
__global__ void compute_u(const float* __restrict__ W,
                          const float* __restrict__ a_src, const float* __restrict__ a_dst,
                          float* __restrict__ u_src, float* __restrict__ u_dst) {
    int k = threadIdx.x;
    if (k >= IN_F) return;
    for (int h = 0; h < HEADS; h++) {
        float s = 0.f, d = 0.f;
        for (int c = 0; c < 64; c++) {
            float w = W[(size_t)k * 256 + h * 64 + c];
            s += w * a_src[h * 64 + c];
            d += w * a_dst[h * 64 + c];
        }
        u_src[k * HEADS + h] = s;
        u_dst[k * HEADS + h] = d;
    }
}

__global__ void compute_v(const float* __restrict__ dproj,
                          const float* __restrict__ a_src, const float* __restrict__ a_dst,
                          float* __restrict__ v_src, float* __restrict__ v_dst) {
    int t = blockIdx.x * blockDim.x + threadIdx.x;
    if (t >= N_D * HEADS) return;
    int d = t >> 2, h = t & 3;
    const float* row = dproj + (size_t)d * 256 + h * 64;
    float s = 0.f, dd = 0.f;
    for (int c = 0; c < 64; c++) {
        s  += row[c] * a_src[h * 64 + c];
        dd += row[c] * a_dst[h * 64 + c];
    }
    v_src[t] = s;
    v_dst[t] = dd;
}

__global__ void vadd_alpha(const int* __restrict__ idx,
                           const float* __restrict__ v_src, const float* __restrict__ v_dst,
                           float4* __restrict__ as4, float4* __restrict__ ad4, int N) {
    int n = blockIdx.x * blockDim.x + threadIdx.x;
    if (n >= N) return;
    int d = idx[n];
    float4 a = as4[n], vs = ((const float4*)v_src)[d];
    float4 b = ad4[n], vd = ((const float4*)v_dst)[d];
    as4[n] = make_float4(a.x + vs.x, a.y + vs.y, a.z + vs.z, a.w + vs.w);
    ad4[n] = make_float4(b.x + vd.x, b.y + vd.y, b.z + vd.z, b.w + vd.w);
}

// as[n][h] = x[n].u[:,h]; warp per node. INLINE_U only for small grids.
template<bool INLINE_U>
__global__ void node_alpha(const float* __restrict__ x,
                           const float* __restrict__ W_or_us, const float* __restrict__ u_dst,
                           const float* __restrict__ a_src, const float* __restrict__ a_dst,
                           float4* __restrict__ as4, float4* __restrict__ ad4, int N) {
    __shared__ float4 us[IN_F], ud[IN_F];
    int t = threadIdx.x;
    if (INLINE_U) {
        if (t < IN_F) {
            float s0=0.f,s1=0.f,s2=0.f,s3=0.f, d0=0.f,d1=0.f,d2=0.f,d3=0.f;
            const float* wr = W_or_us + (size_t)t * 256;
            for (int c = 0; c < 64; c++) {
                float w0 = wr[c], w1 = wr[64 + c], w2 = wr[128 + c], w3 = wr[192 + c];
                s0 += w0 * a_src[c];       d0 += w0 * a_dst[c];
                s1 += w1 * a_src[64 + c];  d1 += w1 * a_dst[64 + c];
                s2 += w2 * a_src[128 + c]; d2 += w2 * a_dst[128 + c];
                s3 += w3 * a_src[192 + c]; d3 += w3 * a_dst[192 + c];
            }
            us[t] = make_float4(s0, s1, s2, s3);
            ud[t] = make_float4(d0, d1, d2, d3);
        }
    } else {
        if (t < IN_F) {
            us[t] = ((const float4*)W_or_us)[t];
            ud[t] = ((const float4*)u_dst)[t];
        }
    }
    __syncthreads();
    int n    = (blockIdx.x * blockDim.x + t) >> 5;
    int lane = t & 31;
    if (n >= N) return;
    float4 xx = ((const float4*)(x + (size_t)n * IN_F))[lane];
    float4 s = make_float4(0.f, 0.f, 0.f, 0.f);
    float4 d = make_float4(0.f, 0.f, 0.f, 0.f);
    int kb = lane * 4;
    float xv[4] = {xx.x, xx.y, xx.z, xx.w};
#pragma unroll
    for (int i = 0; i < 4; i++) {
        float4 uu = us[kb + i];
        s.x += xv[i] * uu.x; s.y += xv[i] * uu.y; s.z += xv[i] * uu.z; s.w += xv[i] * uu.w;
        float4 vv = ud[kb + i];
        d.x += xv[i] * vv.x; d.y += xv[i] * vv.y; d.z += xv[i] * vv.z; d.w += xv[i] * vv.w;
    }
#pragma unroll
    for (int o = 16; o; o >>= 1) {
        s.x += __shfl_xor_sync(0xffffffffu, s.x, o);
        s.y += __shfl_xor_sync(0xffffffffu, s.y, o);
        s.z += __shfl_xor_sync(0xffffffffu, s.z, o);
        s.w += __shfl_xor_sync(0xffffffffu, s.w, o);
        d.x += __shfl_xor_sync(0xffffffffu, d.x, o);
        d.y += __shfl_xor_sync(0xffffffffu, d.y, o);
        d.z += __shfl_xor_sync(0xffffffffu, d.z, o);
        d.w += __shfl_xor_sync(0xffffffffu, d.w, o);
    }
    if (lane == 0) {
        as4[n] = s;
        ad4[n] = d;
    }
}

// ============ fused gather, 4 heads, fp16 h: warp per node ===================
template<typename OutT>
__global__ __launch_bounds__(256) void gat_gather_h4h(
        const int* __restrict__ rowptr, const int* __restrict__ colv,
        const float4* __restrict__ as4, const float4* __restrict__ ad4,
        const __half* __restrict__ h, const float* __restrict__ bias,
        OutT* __restrict__ outbuf, float4* __restrict__ ealpha, int N) {
    __shared__ float4 sal[8][32];
    __shared__ int    ssrc[8][32];
    int wid  = threadIdx.x >> 5;
    int lane = threadIdx.x & 31;
    int n    = (blockIdx.x * blockDim.x + threadIdx.x) >> 5;
    if (n >= N) return;
    int start = rowptr[n], end = rowptr[n + 1];
    bool small = (end - start) <= 32;
    float4 adv = ad4[n];

    float4 ssum = make_float4(0.f, 0.f, 0.f, 0.f);
    float4 myal = make_float4(0.f, 0.f, 0.f, 0.f);
    for (int j = start + lane; j < end; j += 32) {
        float4 v = as4[colv[j]];
        v.x += adv.x; v.y += adv.y; v.z += adv.z; v.w += adv.w;
        v.x = (v.x > 0.f) ? v.x : 0.2f * v.x;
        v.y = (v.y > 0.f) ? v.y : 0.2f * v.y;
        v.z = (v.z > 0.f) ? v.z : 0.2f * v.z;
        v.w = (v.w > 0.f) ? v.w : 0.2f * v.w;
        v.x = __expf(v.x); v.y = __expf(v.y); v.z = __expf(v.z); v.w = __expf(v.w);
        if (!small) ealpha[j] = v;
        myal = v;
        ssum.x += v.x; ssum.y += v.y; ssum.z += v.z; ssum.w += v.w;
    }
#pragma unroll
    for (int o = 16; o; o >>= 1) {
        ssum.x += __shfl_xor_sync(0xffffffffu, ssum.x, o);
        ssum.y += __shfl_xor_sync(0xffffffffu, ssum.y, o);
        ssum.z += __shfl_xor_sync(0xffffffffu, ssum.z, o);
        ssum.w += __shfl_xor_sync(0xffffffffu, ssum.w, o);
    }
    float4 inv = make_float4(1.f / (ssum.x + 1e-16f), 1.f / (ssum.y + 1e-16f),
                             1.f / (ssum.z + 1e-16f), 1.f / (ssum.w + 1e-16f));

    const int hd = lane >> 3;
    float acc[8] = {};
    for (int base = start; base < end; base += 32) {
        int jj = base + lane;
        if (jj < end) {
            ssrc[wid][lane] = colv[jj];
            sal[wid][lane]  = small ? myal : ealpha[jj];
        }
        __syncwarp();
        int kmax = min(32, end - base);
        for (int k = 0; k < kmax; k++) {
            int   s_k = ssrc[wid][k];
            float aA  = ((const float*)&sal[wid][k])[hd];
            float4 raw = ((const float4*)(h + (size_t)s_k * 256))[lane];
            const __half2* hh = (const __half2*)&raw;
#pragma unroll
            for (int i = 0; i < 4; i++) {
                float2 f = __half22float2(hh[i]);
                acc[2 * i]     += aA * f.x;
                acc[2 * i + 1] += aA * f.y;
            }
        }
        __syncwarp();
    }

    float invA = (hd == 0) ? inv.x : (hd == 1) ? inv.y : (hd == 2) ? inv.z : inv.w;
    float4 b0 = ((const float4*)bias)[2 * lane];
    float4 b1 = ((const float4*)bias)[2 * lane + 1];
    float o0 = fmaxf(acc[0] * invA + b0.x, 0.f), o1 = fmaxf(acc[1] * invA + b0.y, 0.f);
    float o2 = fmaxf(acc[2] * invA + b0.z, 0.f), o3 = fmaxf(acc[3] * invA + b0.w, 0.f);
    float o4v = fmaxf(acc[4] * invA + b1.x, 0.f), o5 = fmaxf(acc[5] * invA + b1.y, 0.f);
    float o6 = fmaxf(acc[6] * invA + b1.z, 0.f), o7 = fmaxf(acc[7] * invA + b1.w, 0.f);
    if constexpr (sizeof(OutT) == 2) {
        __half2 p[4] = {__floats2half2_rn(o0, o1), __floats2half2_rn(o2, o3),
                        __floats2half2_rn(o4v, o5), __floats2half2_rn(o6, o7)};
        *(uint4*)(outbuf + (size_t)n * 256 + lane * 8) = *(const uint4*)p;
    } else {
        float4* o4p = (float4*)((float*)outbuf + (size_t)n * 256);
        o4p[2 * lane]     = make_float4(o0, o1, o2, o3);
        o4p[2 * lane + 1] = make_float4(o4v, o5, o6, o7);
    }
}

// ============ fused gather, 1 head: warp per node ============================
template<typename HT, int C, int ACT>
__global__ void gat_gather1(const int* __restrict__ rowptr, const int* __restrict__ colv,
                            const float* __restrict__ as_, const float* __restrict__ ad_,
                            const HT* __restrict__ h, const float* __restrict__ bias,
                            float* __restrict__ outbuf, float* __restrict__ ealpha, int N) {
    int n    = (blockIdx.x * blockDim.x + threadIdx.x) >> 5;
    int lane = threadIdx.x & 31;
    if (n >= N) return;
    int start = rowptr[n], end = rowptr[n + 1];
    bool small = (end - start) <= 32;
    float adv = ad_[n];

    float ssum = 0.f, myal = 0.f;
    for (int j = start + lane; j < end; j += 32) {
        float v = as_[colv[j]] + adv;
        v = (v > 0.f) ? v : 0.2f * v;
        v = __expf(v);
        if (!small) ealpha[j] = v;
        myal = v;
        ssum += v;
    }
#pragma unroll
    for (int o = 16; o; o >>= 1) ssum += __shfl_xor_sync(0xffffffffu, ssum, o);
    float inv = 1.f / (ssum + 1e-16f);

    float acc0 = 0.f, acc1 = 0.f;
    for (int base = start; base < end; base += 32) {
        int jj = base + lane;
        int srcv = 0; float al = 0.f;
        if (jj < end) {
            srcv = colv[jj];
            al = small ? myal : ealpha[jj];
        }
        int kmax = min(32, end - base);
        for (int k = 0; k < kmax; k++) {
            int   s_k = __shfl_sync(0xffffffffu, srcv, k);
            float a_k = __shfl_sync(0xffffffffu, al,   k);
            const HT* hp = h + (size_t)s_k * C;
            acc0 += a_k * to_f(hp[lane]);
            if (C == 64) acc1 += a_k * to_f(hp[lane + 32]);
        }
    }

    if (ACT == 2) {
        float v = acc0 * inv + bias[lane];
        float m = v;
#pragma unroll
        for (int o = 16; o; o >>= 1) m = fmaxf(m, __shfl_xor_sync(0xffffffffu, m, o));
        float ex = __expf(v - m);
        float se = ex;
#pragma unroll
        for (int o = 16; o; o >>= 1) se += __shfl_xor_sync(0xffffffffu, se, o);
        outbuf[(size_t)n * 32 + lane] = (v - m) - logf(se);
    } else {
        outbuf[(size_t)n * C + lane] = acc0 * inv + bias[lane];
        if (C == 64)
            outbuf[(size_t)n * C + lane + 32] = acc1 * inv + bias[lane + 32];
    }
}

// --------------------------------- host side --------------------------------
template<typename T>
static inline T* sym(const void* s) {
    void* p = nullptr;
    cudaGetSymbolAddress(&p, s);
    return (T*)p;
}

extern "C" void kernel_launch(void* const* d_in, const int* in_sizes, int n_in,
                              void* d_out, int out_size) {
    const float* dept_x  = (const float*)d_in[0];
    const int*   dept_ei = (const int*)  d_in[1];
    const float* emp_x   = (const float*)d_in[2];
    const int*   emp_ei  = (const int*)  d_in[3];
    const int*   dept_ix = (const int*)  d_in[4];
    const float* W_d1    = (const float*)d_in[5];
    const float* as_d1   = (const float*)d_in[6];
    const float* ad_d1   = (const float*)d_in[7];
    const float* b_d1    = (const float*)d_in[8];
    const float* W_d2    = (const float*)d_in[9];
    const float* as_d2   = (const float*)d_in[10];
    const float* ad_d2   = (const float*)d_in[11];
    const float* b_d2    = (const float*)d_in[12];
    const float* W_e1    = (const float*)d_in[13];
    const float* as_e1   = (const float*)d_in[14];
    const float* ad_e1   = (const float*)d_in[15];
    const float* b_e1    = (const float*)d_in[16];
    const float* W_e2    = (const float*)d_in[17];
    const float* as_e2   = (const float*)d_in[18];
    const float* ad_e2   = (const float*)d_in[19];
    const float* b_e2    = (const float*)d_in[20];
    float* out = (float*)d_out;

    static cudaStream_t side = nullptr, side2 = nullptr;
    static cudaEvent_t evF = nullptr, evC = nullptr, evV = nullptr;
    if (!side) {
        cudaStreamCreateWithFlags(&side, cudaStreamNonBlocking);
        cudaStreamCreateWithFlags(&side2, cudaStreamNonBlocking);
        cudaEventCreateWithFlags(&evF, cudaEventDisableTiming);
        cudaEventCreateWithFlags(&evC, cudaEventDisableTiming);
        cudaEventCreateWithFlags(&evV, cudaEventDisableTiming);
    }

    __half *p_d_h1h = sym<__half>(g_d_h1h), *p_e_h1h = sym<__half>(g_e_h1h);
    __half *p_e_out1h = sym<__half>(g_e_out1h), *p_e_h2h = sym<__half>(g_e_h2h);
    float *p_d_as1 = sym<float>(g_d_as1), *p_d_ad1 = sym<float>(g_d_ad1);
    float *p_d_out1 = sym<float>(g_d_out1), *p_d_h2 = sym<float>(g_d_h2);
    float *p_d_as2 = sym<float>(g_d_as2), *p_d_ad2 = sym<float>(g_d_ad2), *p_d_out2 = sym<float>(g_d_out2);
    float *p_dproj = sym<float>(g_dproj);
    float *p_e_as1 = sym<float>(g_e_as1), *p_e_ad1 = sym<float>(g_e_ad1);
    float *p_e_as2 = sym<float>(g_e_as2), *p_e_ad2 = sym<float>(g_e_ad2);
    float *p_usrc = sym<float>(g_u_src), *p_udst = sym<float>(g_u_dst);
    float *p_vsrc = sym<float>(g_v_src), *p_vdst = sym<float>(g_v_dst);
    float4 *p_ealpha = sym<float4>(g_ealpha);

    int *deg_d = sym<int>(g_deg_d), *cur_d = sym<int>(g_cur_d), *row_d = sym<int>(g_row_d);
    int *col_d = sym<int>(g_colv_d);
    int *degcur_e = sym<int>(g_degcur_e);
    int *deg_e = degcur_e, *cur_e = degcur_e + N_E;
    int *row_e = sym<int>(g_row_e), *col_e = sym<int>(g_colv_e), *bs_e = sym<int>(g_bs_e);

    const int TB = 256;

    // ---- fork ----
    cudaEventRecord(evF, 0);
    cudaStreamWaitEvent(side, evF, 0);
    cudaStreamWaitEvent(side2, evF, 0);

    // side2: dept CSR build (concurrent with dept1 GEMM)
    build_csr_small<<<1, 1024, 0, side2>>>(dept_ei, E_D, N_D, deg_d, cur_d, row_d, col_d);
    cudaEventRecord(evC, side2);

    // side: dept compute chain
    {
        dim3 g(cdiv(HEADS * DHC, 128), cdiv(N_D, 128));
        gemm_f16<__half><<<g, 256, 0, side>>>(dept_x, W_d1, p_d_h1h, N_D, HEADS * DHC, IN_F, nullptr, nullptr);
    }
    node_alpha<true><<<cdiv(N_D * 32, TB), TB, 0, side>>>(
        dept_x, W_d1, nullptr, as_d1, ad_d1, (float4*)p_d_as1, (float4*)p_d_ad1, N_D);
    cudaStreamWaitEvent(side, evC, 0);
    gat_gather_h4h<float><<<cdiv(N_D * 32, TB), TB, 0, side>>>(
        row_d, col_d, (const float4*)p_d_as1, (const float4*)p_d_ad1,
        p_d_h1h, b_d1, p_d_out1, p_ealpha, N_D);
    {
        dim3 g(1, cdiv(N_D, 64));
        gemm64a<<<g, 256, 0, side>>>(p_d_out1, W_d2, p_d_h2, N_D, DHC, HEADS * DHC,
                                     as_d2, ad_d2, p_d_as2, p_d_ad2);
    }
    gat_gather1<float, DHC, 0><<<cdiv(N_D * 32, TB), TB, 0, side>>>(
        row_d, col_d, p_d_as2, p_d_ad2, p_d_h2, b_d2, p_d_out2, (float*)p_ealpha, N_D);
    {
        dim3 g(cdiv(HEADS * EHC, 128), cdiv(N_D, 128));
        gemm_tc<float><<<g, 256, 0, side>>>(p_d_out2, W_e1 + (size_t)IN_F * HEADS * EHC, p_dproj,
                                            N_D, HEADS * EHC, DHC, nullptr, nullptr);
    }
    compute_v<<<cdiv(N_D * HEADS, 256), 256, 0, side>>>(p_dproj, as_e1, ad_e1, p_vsrc, p_vdst);
    cudaEventRecord(evV, side);

    // main: emp CSR build + u precompute + emp alpha partial — overlaps dept chain
    cudaMemsetAsync(degcur_e, 0, sizeof(int) * 2 * N_E);
    compute_u<<<1, 128>>>(W_e1, as_e1, ad_e1, p_usrc, p_udst);
    {
        int nb = cdiv(N_E, 256);
        deg_count<<<cdiv(E_E, TB), TB>>>(emp_ei, E_E, deg_e);
        block_sum<<<nb, 256>>>(deg_e, N_E, bs_e);
        scan_bsums<<<1, 32>>>(bs_e, nb, row_e, E_E + N_E, N_E);
        scan_final<<<nb, 256>>>(deg_e, bs_e, N_E, row_e);
        fill_csr<<<cdiv(E_E + N_E, TB), TB>>>(emp_ei, E_E, N_E, row_e, cur_e, col_e);
    }
    node_alpha<false><<<cdiv(N_E * 32, TB), TB>>>(
        emp_x, p_usrc, p_udst, nullptr, nullptr, (float4*)p_e_as1, (float4*)p_e_ad1, N_E);

    // ---- join: main waits for side's dproj + v, then finishes alphas ----
    cudaStreamWaitEvent(0, evV, 0);
    vadd_alpha<<<cdiv(N_E, TB), TB>>>(dept_ix, p_vsrc, p_vdst,
                                      (float4*)p_e_as1, (float4*)p_e_ad1, N_E);

    // ============ emp layer 1 (fp16 HMMA) ============
    {
        dim3 g(cdiv(HEADS * EHC, 128), cdiv(N_E, 128));
        gemm_f16<__half><<<g, 256>>>(emp_x, W_e1, p_e_h1h, N_E, HEADS * EHC, IN_F, p_dproj, dept_ix);
    }
    gat_gather_h4h<__half><<<cdiv(N_E * 32, TB), TB>>>(
        row_e, col_e, (const float4*)p_e_as1, (const float4*)p_e_ad1,
        p_e_h1h, b_e1, p_e_out1h, p_ealpha, N_E);

    // ============ emp layer 2: fp16 HMMA GEMM + fused alpha + log_softmax ====
    gemm_n32_h<<<cdiv(N_E, 128), 256>>>(p_e_out1h, W_e2, p_e_h2h, N_E, HEADS * EHC,
                                        as_e2, ad_e2, p_e_as2, p_e_ad2);
    gat_gather1<__half, OUTC, 2><<<cdiv(N_E * 32, TB), TB>>>(
        row_e, col_e, p_e_as2, p_e_ad2, p_e_h2h, b_e2, out, (float*)p_ealpha, N_E);
}

// round 12
// speedup vs baseline: 1.0490x; 1.0490x over previous
#include <cuda_runtime.h>
#include <cuda_fp16.h>
#include <cstdint>

#define N_D 2000
#define E_D 32000
#define N_E 50000
#define E_E 800000
#define IN_F 128
#define DHC 64
#define EHC 64
#define OUTC 32
#define HEADS 4

// ------------------------- scratch (device globals) -------------------------
__device__ __half g_d_h1h[N_D * HEADS * DHC];
__device__ float  g_d_as1[N_D * HEADS];
__device__ float  g_d_ad1[N_D * HEADS];
__device__ float  g_d_out1[N_D * HEADS * DHC];
__device__ float  g_d_h2 [N_D * DHC];
__device__ float  g_d_as2[N_D];
__device__ float  g_d_ad2[N_D];
__device__ float  g_d_out2[N_D * DHC];
__device__ float  g_dproj [N_D * HEADS * EHC];

__device__ __half g_e_h1h[N_E * HEADS * EHC];
__device__ float  g_e_as1[N_E * HEADS];
__device__ float  g_e_ad1[N_E * HEADS];
__device__ __half g_e_out1h[N_E * HEADS * EHC];
__device__ __half g_e_h2h[N_E * OUTC];
__device__ float  g_e_as2[N_E];
__device__ float  g_e_ad2[N_E];

// alpha-precompute scratch
__device__ float g_u_src[IN_F * HEADS];
__device__ float g_u_dst[IN_F * HEADS];
__device__ float g_v_src[N_D * HEADS];
__device__ float g_v_dst[N_D * HEADS];

// per-edge alpha spill (4 heads)
__device__ float4 g_ealpha[E_E + N_E];

// CSR scratch
__device__ int g_deg_d [N_D];
__device__ int g_cur_d [N_D];
__device__ int g_row_d [N_D + 1];
__device__ int g_colv_d[E_D + N_D];
__device__ int g_degcur_e[2 * N_E];
__device__ int g_row_e [N_E + 1];
__device__ int g_colv_e[E_E + N_E];
__device__ int g_bs_e  [256];

static inline int cdiv(int a, int b) { return (a + b - 1) / b; }

__device__ __forceinline__ float to_f(float x)  { return x; }
__device__ __forceinline__ float to_f(__half x) { return __half2float(x); }

// ================== dept CSR: single-block build ============================
__global__ void build_csr_small(const int* __restrict__ ei, int E, int N,
                                int* __restrict__ deg, int* __restrict__ cur,
                                int* __restrict__ rowptr, int* __restrict__ colv) {
    __shared__ int sh[1024];
    __shared__ int carry;
    int tid = threadIdx.x;
    for (int i = tid; i < N; i += 1024) { deg[i] = 0; cur[i] = 0; }
    __syncthreads();
    for (int i = tid; i < E; i += 1024) atomicAdd(&deg[ei[E + i]], 1);
    if (tid == 0) carry = 0;
    __syncthreads();
    for (int base = 0; base < N; base += 1024) {
        int v = (base + tid < N) ? (deg[base + tid] + 1) : 0;
        sh[tid] = v;
        __syncthreads();
        for (int off = 1; off < 1024; off <<= 1) {
            int x = (tid >= off) ? sh[tid - off] : 0;
            __syncthreads();
            sh[tid] += x;
            __syncthreads();
        }
        if (base + tid < N) rowptr[base + tid] = carry + sh[tid] - v;
        __syncthreads();
        if (tid == 0) carry += sh[1023];
        __syncthreads();
    }
    if (tid == 0) rowptr[N] = carry;
    __syncthreads();
    for (int i = tid; i < E + N; i += 1024) {
        int s, d;
        if (i < E) { s = ei[i]; d = ei[E + i]; }
        else       { s = d = i - E; }
        colv[rowptr[d] + atomicAdd(&cur[d], 1)] = s;
    }
}

// =============================== emp CSR build ===============================
__global__ void deg_count(const int* __restrict__ ei, int E, int* __restrict__ deg) {
    int t = blockIdx.x * blockDim.x + threadIdx.x;
    if (t < E) atomicAdd(&deg[ei[E + t]], 1);
}

__global__ void block_sum(const int* __restrict__ deg, int N, int* __restrict__ bsum) {
    __shared__ int sh[256];
    int i = blockIdx.x * 256 + threadIdx.x;
    sh[threadIdx.x] = (i < N) ? (deg[i] + 1) : 0;
    __syncthreads();
    for (int off = 128; off; off >>= 1) {
        if (threadIdx.x < off) sh[threadIdx.x] += sh[threadIdx.x + off];
        __syncthreads();
    }
    if (threadIdx.x == 0) bsum[blockIdx.x] = sh[0];
}

__global__ void scan_bsums(int* __restrict__ bsum, int nb, int* __restrict__ rowptr,
                           int total, int N) {
    if (threadIdx.x == 0) {
        int acc = 0;
        for (int i = 0; i < nb; i++) { int v = bsum[i]; bsum[i] = acc; acc += v; }
        rowptr[N] = total;
    }
}

__global__ void scan_final(const int* __restrict__ deg, const int* __restrict__ bsum,
                           int N, int* __restrict__ rowptr) {
    __shared__ int sh[256];
    int i = blockIdx.x * 256 + threadIdx.x;
    int v = (i < N) ? (deg[i] + 1) : 0;
    sh[threadIdx.x] = v;
    __syncthreads();
    for (int off = 1; off < 256; off <<= 1) {
        int x = (threadIdx.x >= off) ? sh[threadIdx.x - off] : 0;
        __syncthreads();
        sh[threadIdx.x] += x;
        __syncthreads();
    }
    if (i < N) rowptr[i] = bsum[blockIdx.x] + sh[threadIdx.x] - v;
}

__global__ void fill_csr(const int* __restrict__ ei, int E, int N,
                         const int* __restrict__ rowptr, int* __restrict__ cur,
                         int* __restrict__ colv) {
    int t = blockIdx.x * blockDim.x + threadIdx.x;
    if (t >= E + N) return;
    int src, dst;
    if (t < E) { src = ei[t]; dst = ei[E + t]; }
    else       { src = dst = t - E; }
    int pos = rowptr[dst] + atomicAdd(&cur[dst], 1);
    colv[pos] = src;
}

// ======================= MMA helpers ========================================
__device__ __forceinline__ uint32_t f2tf32(float x) {
    uint32_t r;
    asm("cvt.rna.tf32.f32 %0, %1;" : "=r"(r) : "f"(x));
    return r;
}

__device__ __forceinline__ void mma_tf32(float (&d)[4], const uint32_t* a, const uint32_t* b) {
    asm volatile(
        "mma.sync.aligned.m16n8k8.row.col.f32.tf32.tf32.f32 "
        "{%0,%1,%2,%3}, {%4,%5,%6,%7}, {%8,%9}, {%0,%1,%2,%3};"
        : "+f"(d[0]), "+f"(d[1]), "+f"(d[2]), "+f"(d[3])
        : "r"(a[0]), "r"(a[1]), "r"(a[2]), "r"(a[3]), "r"(b[0]), "r"(b[1]));
}

__device__ __forceinline__ void mma_f16(float (&d)[4], const uint32_t* a, const uint32_t* b) {
    asm volatile(
        "mma.sync.aligned.m16n8k16.row.col.f32.f16.f16.f32 "
        "{%0,%1,%2,%3}, {%4,%5,%6,%7}, {%8,%9}, {%0,%1,%2,%3};"
        : "+f"(d[0]), "+f"(d[1]), "+f"(d[2]), "+f"(d[3])
        : "r"(a[0]), "r"(a[1]), "r"(a[2]), "r"(a[3]), "r"(b[0]), "r"(b[1]));
}

#define AS_STRIDE 20
#define BS_STRIDE 136

// =================== tf32 GEMM 128x128 (main GEMM path) ======================
template<typename OutT>
__global__ __launch_bounds__(256) void gemm_tc(
        const float* __restrict__ A, const float* __restrict__ B,
        OutT* __restrict__ C, int M, int N, int K,
        const float* __restrict__ add, const int* __restrict__ idx) {
    __shared__ uint32_t As[128 * AS_STRIDE];
    __shared__ uint32_t Bs[16 * BS_STRIDE];

    const int t = threadIdx.x;
    const int lane = t & 31;
    const int warp = t >> 5;
    const int warpM = warp & 1;
    const int warpN = warp >> 1;
    const int g  = lane >> 2;
    const int tq = lane & 3;
    const int rowbase = blockIdx.y * 128;
    const int colbase = blockIdx.x * 128;

    const int am = t >> 1;
    const int ak = (t & 1) * 8;
    const int bk = t >> 4;
    const int bn = (t & 15) * 8;

    float acc[4][4][4] = {};
    float av[8], bv[8];

    {
        float4 z = make_float4(0.f, 0.f, 0.f, 0.f);
        float4 v0 = z, v1 = z;
        if (rowbase + am < M) {
            v0 = *(const float4*)&A[(size_t)(rowbase + am) * K + ak];
            v1 = *(const float4*)&A[(size_t)(rowbase + am) * K + ak + 4];
        }
        av[0]=v0.x; av[1]=v0.y; av[2]=v0.z; av[3]=v0.w;
        av[4]=v1.x; av[5]=v1.y; av[6]=v1.z; av[7]=v1.w;
        float4 w0 = *(const float4*)&B[(size_t)bk * N + colbase + bn];
        float4 w1 = *(const float4*)&B[(size_t)bk * N + colbase + bn + 4];
        bv[0]=w0.x; bv[1]=w0.y; bv[2]=w0.z; bv[3]=w0.w;
        bv[4]=w1.x; bv[5]=w1.y; bv[6]=w1.z; bv[7]=w1.w;
    }

    for (int k0 = 0; k0 < K; k0 += 16) {
#pragma unroll
        for (int i = 0; i < 8; i++) As[am * AS_STRIDE + ak + i] = f2tf32(av[i]);
#pragma unroll
        for (int i = 0; i < 8; i++) Bs[bk * BS_STRIDE + bn + i] = f2tf32(bv[i]);
        __syncthreads();

        if (k0 + 16 < K) {
            const int kn = k0 + 16;
            float4 z = make_float4(0.f, 0.f, 0.f, 0.f);
            float4 v0 = z, v1 = z;
            if (rowbase + am < M) {
                v0 = *(const float4*)&A[(size_t)(rowbase + am) * K + kn + ak];
                v1 = *(const float4*)&A[(size_t)(rowbase + am) * K + kn + ak + 4];
            }
            av[0]=v0.x; av[1]=v0.y; av[2]=v0.z; av[3]=v0.w;
            av[4]=v1.x; av[5]=v1.y; av[6]=v1.z; av[7]=v1.w;
            float4 w0 = *(const float4*)&B[(size_t)(kn + bk) * N + colbase + bn];
            float4 w1 = *(const float4*)&B[(size_t)(kn + bk) * N + colbase + bn + 4];
            bv[0]=w0.x; bv[1]=w0.y; bv[2]=w0.z; bv[3]=w0.w;
            bv[4]=w1.x; bv[5]=w1.y; bv[6]=w1.z; bv[7]=w1.w;
        }

#pragma unroll
        for (int s = 0; s < 2; s++) {
            uint32_t ah[4][4], bh[4][2];
#pragma unroll
            for (int mi = 0; mi < 4; mi++) {
                int r0 = (warpM * 64 + mi * 16 + g) * AS_STRIDE;
                int r1 = r0 + 8 * AS_STRIDE;
                int c0 = s * 8 + tq;
                ah[mi][0] = As[r0 + c0];     ah[mi][1] = As[r1 + c0];
                ah[mi][2] = As[r0 + c0 + 4]; ah[mi][3] = As[r1 + c0 + 4];
            }
#pragma unroll
            for (int ni = 0; ni < 4; ni++) {
                int bc = warpN * 32 + ni * 8 + g;
                int kr0 = (s * 8 + tq) * BS_STRIDE;
                int kr1 = (s * 8 + tq + 4) * BS_STRIDE;
                bh[ni][0] = Bs[kr0 + bc]; bh[ni][1] = Bs[kr1 + bc];
            }
#pragma unroll
            for (int mi = 0; mi < 4; mi++)
#pragma unroll
                for (int ni = 0; ni < 4; ni++)
                    mma_tf32(acc[mi][ni], ah[mi], bh[ni]);
        }
        __syncthreads();
    }

#pragma unroll
    for (int mi = 0; mi < 4; mi++) {
        int row0 = rowbase + warpM * 64 + mi * 16 + g;
        int row1 = row0 + 8;
        const float* ap0 = nullptr;
        const float* ap1 = nullptr;
        if (idx) {
            if (row0 < M) ap0 = add + (size_t)idx[row0] * N;
            if (row1 < M) ap1 = add + (size_t)idx[row1] * N;
        }
#pragma unroll
        for (int ni = 0; ni < 4; ni++) {
            int col = colbase + warpN * 32 + ni * 8 + 2 * tq;
            if (row0 < M) {
                float vx = acc[mi][ni][0], vy = acc[mi][ni][1];
                if (ap0) { vx += ap0[col]; vy += ap0[col + 1]; }
                if constexpr (sizeof(OutT) == 2) {
                    *(__half2*)&C[(size_t)row0 * N + col] = __floats2half2_rn(vx, vy);
                } else {
                    *(float2*)&C[(size_t)row0 * N + col] = make_float2(vx, vy);
                }
            }
            if (row1 < M) {
                float vx = acc[mi][ni][2], vy = acc[mi][ni][3];
                if (ap1) { vx += ap1[col]; vy += ap1[col + 1]; }
                if constexpr (sizeof(OutT) == 2) {
                    *(__half2*)&C[(size_t)row1 * N + col] = __floats2half2_rn(vx, vy);
                } else {
                    *(float2*)&C[(size_t)row1 * N + col] = make_float2(vx, vy);
                }
            }
        }
    }
}

// ============ fp16 HMMA GEMM, N=32, A fp16, fused alpha-dot epilogue ========
#define AH_STRIDE 24
#define BH_STRIDE 24
__global__ __launch_bounds__(256) void gemm_n32_h(
        const __half* __restrict__ A, const float* __restrict__ B,
        __half* __restrict__ C, int M, int K,
        const float* __restrict__ a_src, const float* __restrict__ a_dst,
        float* __restrict__ as_out, float* __restrict__ ad_out) {
    __shared__ __half As_h[128 * AH_STRIDE];
    __shared__ __half Bst[32 * BH_STRIDE];
    __shared__ float sa[32], sd[32];

    const int t = threadIdx.x;
    const int lane = t & 31;
    const int warp = t >> 5;
    const int g  = lane >> 2;
    const int tq = lane & 3;
    const int rowbase = blockIdx.x * 128;

    const int am = t >> 1;
    const int ah_off = (t & 1) * 8;
    const int bk = t >> 4;
    const int bc = (t & 15) * 2;

    if (t < 32) { sa[t] = a_src[t]; sd[t] = a_dst[t]; }

    float acc[4][4] = {};
    uint4  a_pre = make_uint4(0, 0, 0, 0);
    float2 b_pre;

    if (rowbase + am < M)
        a_pre = *(const uint4*)&A[(size_t)(rowbase + am) * K + ah_off];
    b_pre = *(const float2*)&B[(size_t)bk * 32 + bc];

    for (int k0 = 0; k0 < K; k0 += 16) {
        *(uint4*)&As_h[am * AH_STRIDE + ah_off] = a_pre;
        Bst[(bc + 0) * BH_STRIDE + bk] = __float2half_rn(b_pre.x);
        Bst[(bc + 1) * BH_STRIDE + bk] = __float2half_rn(b_pre.y);
        __syncthreads();

        if (k0 + 16 < K) {
            a_pre = make_uint4(0, 0, 0, 0);
            if (rowbase + am < M)
                a_pre = *(const uint4*)&A[(size_t)(rowbase + am) * K + k0 + 16 + ah_off];
            b_pre = *(const float2*)&B[(size_t)(k0 + 16 + bk) * 32 + bc];
        }

        uint32_t ar[4];
        int r0 = (warp * 16 + g) * AH_STRIDE;
        int r1 = r0 + 8 * AH_STRIDE;
        ar[0] = *(const uint32_t*)&As_h[r0 + 2 * tq];
        ar[1] = *(const uint32_t*)&As_h[r1 + 2 * tq];
        ar[2] = *(const uint32_t*)&As_h[r0 + 2 * tq + 8];
        ar[3] = *(const uint32_t*)&As_h[r1 + 2 * tq + 8];
#pragma unroll
        for (int ni = 0; ni < 4; ni++) {
            uint32_t br[2];
            int cb = (ni * 8 + g) * BH_STRIDE;
            br[0] = *(const uint32_t*)&Bst[cb + 2 * tq];
            br[1] = *(const uint32_t*)&Bst[cb + 2 * tq + 8];
            mma_f16(acc[ni], ar, br);
        }
        __syncthreads();
    }

    int row0 = rowbase + warp * 16 + g;
    int row1 = row0 + 8;
    float s0 = 0.f, s1 = 0.f, d0 = 0.f, d1 = 0.f;
#pragma unroll
    for (int ni = 0; ni < 4; ni++) {
        int c0 = ni * 8 + 2 * tq;
        float a0 = sa[c0], a1 = sa[c0 + 1];
        float b0 = sd[c0], b1 = sd[c0 + 1];
        s0 += acc[ni][0] * a0 + acc[ni][1] * a1;
        s1 += acc[ni][2] * a0 + acc[ni][3] * a1;
        d0 += acc[ni][0] * b0 + acc[ni][1] * b1;
        d1 += acc[ni][2] * b0 + acc[ni][3] * b1;
        if (row0 < M) *(__half2*)&C[(size_t)row0 * 32 + c0] = __floats2half2_rn(acc[ni][0], acc[ni][1]);
        if (row1 < M) *(__half2*)&C[(size_t)row1 * 32 + c0] = __floats2half2_rn(acc[ni][2], acc[ni][3]);
    }
#pragma unroll
    for (int off = 1; off <= 2; off <<= 1) {
        s0 += __shfl_xor_sync(0xffffffffu, s0, off);
        s1 += __shfl_xor_sync(0xffffffffu, s1, off);
        d0 += __shfl_xor_sync(0xffffffffu, d0, off);
        d1 += __shfl_xor_sync(0xffffffffu, d1, off);
    }
    if (tq == 0) {
        if (row0 < M) { as_out[row0] = s0; ad_out[row0] = d0; }
        if (row1 < M) { as_out[row1] = s1; ad_out[row1] = d1; }
    }
}

// ============ GEMM 64x64x16 (dept2) with fused alpha-dot epilogue ===========
__global__ void gemm64a(const float* __restrict__ A, const float* __restrict__ B,
                        float* __restrict__ C, int M, int N, int K,
                        const float* __restrict__ a_src, const float* __restrict__ a_dst,
                        float* __restrict__ as_out, float* __restrict__ ad_out) {
    __shared__ float As[16][64];
    __shared__ float Bs[16][64];
    __shared__ float sa[64], sd[64];
    const int t  = threadIdx.x;
    const int tx = t & 15;
    const int ty = t >> 4;
    const int rowbase = blockIdx.y * 64;
    const int ar = t >> 2;
    const int ak = (t & 3) * 4;
    const int bk = t >> 4;
    const int bc = (t & 15) * 4;

    if (t < 64) { sa[t] = a_src[t]; sd[t] = a_dst[t]; }

    float acc[4][4] = {};
    for (int k0 = 0; k0 < K; k0 += 16) {
        float4 av = make_float4(0.f, 0.f, 0.f, 0.f);
        if (rowbase + ar < M)
            av = *(const float4*)&A[(size_t)(rowbase + ar) * K + k0 + ak];
        As[ak + 0][ar] = av.x; As[ak + 1][ar] = av.y;
        As[ak + 2][ar] = av.z; As[ak + 3][ar] = av.w;
        float4 bv = *(const float4*)&B[(size_t)(k0 + bk) * N + bc];
        *(float4*)&Bs[bk][bc] = bv;
        __syncthreads();
#pragma unroll
        for (int kk = 0; kk < 16; kk++) {
            float4 a = *(const float4*)&As[kk][ty * 4];
            float4 b = *(const float4*)&Bs[kk][tx * 4];
            acc[0][0] += a.x * b.x; acc[0][1] += a.x * b.y; acc[0][2] += a.x * b.z; acc[0][3] += a.x * b.w;
            acc[1][0] += a.y * b.x; acc[1][1] += a.y * b.y; acc[1][2] += a.y * b.z; acc[1][3] += a.y * b.w;
            acc[2][0] += a.z * b.x; acc[2][1] += a.z * b.y; acc[2][2] += a.z * b.z; acc[2][3] += a.z * b.w;
            acc[3][0] += a.w * b.x; acc[3][1] += a.w * b.y; acc[3][2] += a.w * b.z; acc[3][3] += a.w * b.w;
        }
        __syncthreads();
    }
#pragma unroll
    for (int i = 0; i < 4; i++) {
        int row = rowbase + ty * 4 + i;
        float ps = 0.f, pd = 0.f;
#pragma unroll
        for (int j = 0; j < 4; j++) {
            int col = tx * 4 + j;
            ps += acc[i][j] * sa[col];
            pd += acc[i][j] * sd[col];
        }
#pragma unroll
        for (int off = 1; off <= 8; off <<= 1) {
            ps += __shfl_xor_sync(0xffffffffu, ps, off);
            pd += __shfl_xor_sync(0xffffffffu, pd, off);
        }
        if (row < M) {
            *(float4*)&C[(size_t)row * N + tx * 4] =
                make_float4(acc[i][0], acc[i][1], acc[i][2], acc[i][3]);
            if (tx == 0) { as_out[row] = ps; ad_out[row] = pd; }
        }
    }
}

// -------------------- alpha precompute ----------------------
__global__ void compute_u(const float* __restrict__ W,
                          const float* __restrict__ a_src, const float* __restrict__ a_dst,
                          float* __restrict__ u_src, float* __restrict__ u_dst) {
    int k = threadIdx.x;
    if (k >= IN_F) return;
    for (int h = 0; h < HEADS; h++) {
        float s = 0.f, d = 0.f;
        for (int c = 0; c < 64; c++) {
            float w = W[(size_t)k * 256 + h * 64 + c];
            s += w * a_src[h * 64 + c];
            d += w * a_dst[h * 64 + c];
        }
        u_src[k * HEADS + h] = s;
        u_dst[k * HEADS + h] = d;
    }
}

__global__ void compute_v(const float* __restrict__ dproj,
                          const float* __restrict__ a_src, const float* __restrict__ a_dst,
                          float* __restrict__ v_src, float* __restrict__ v_dst) {
    int t = blockIdx.x * blockDim.x + threadIdx.x;
    if (t >= N_D * HEADS) return;
    int d = t >> 2, h = t & 3;
    const float* row = dproj + (size_t)d * 256 + h * 64;
    float s = 0.f, dd = 0.f;
    for (int c = 0; c < 64; c++) {
        s  += row[c] * a_src[h * 64 + c];
        dd += row[c] * a_dst[h * 64 + c];
    }
    v_src[t] = s;
    v_dst[t] = dd;
}

__global__ void vadd_alpha(const int* __restrict__ idx,
                           const float* __restrict__ v_src, const float* __restrict__ v_dst,
                           float4* __restrict__ as4, float4* __restrict__ ad4, int N) {
    int n = blockIdx.x * blockDim.x + threadIdx.x;
    if (n >= N) return;
    int d = idx[n];
    float4 a = as4[n], vs = ((const float4*)v_src)[d];
    float4 b = ad4[n], vd = ((const float4*)v_dst)[d];
    as4[n] = make_float4(a.x + vs.x, a.y + vs.y, a.z + vs.z, a.w + vs.w);
    ad4[n] = make_float4(b.x + vd.x, b.y + vd.y, b.z + vd.z, b.w + vd.w);
}

// as[n][h] = x[n].u[:,h]; warp per node. INLINE_U only for small grids.
template<bool INLINE_U>
__global__ void node_alpha(const float* __restrict__ x,
                           const float* __restrict__ W_or_us, const float* __restrict__ u_dst,
                           const float* __restrict__ a_src, const float* __restrict__ a_dst,
                           float4* __restrict__ as4, float4* __restrict__ ad4, int N) {
    __shared__ float4 us[IN_F], ud[IN_F];
    int t = threadIdx.x;
    if (INLINE_U) {
        if (t < IN_F) {
            float s0=0.f,s1=0.f,s2=0.f,s3=0.f, d0=0.f,d1=0.f,d2=0.f,d3=0.f;
            const float* wr = W_or_us + (size_t)t * 256;
            for (int c = 0; c < 64; c++) {
                float w0 = wr[c], w1 = wr[64 + c], w2 = wr[128 + c], w3 = wr[192 + c];
                s0 += w0 * a_src[c];       d0 += w0 * a_dst[c];
                s1 += w1 * a_src[64 + c];  d1 += w1 * a_dst[64 + c];
                s2 += w2 * a_src[128 + c]; d2 += w2 * a_dst[128 + c];
                s3 += w3 * a_src[192 + c]; d3 += w3 * a_dst[192 + c];
            }
            us[t] = make_float4(s0, s1, s2, s3);
            ud[t] = make_float4(d0, d1, d2, d3);
        }
    } else {
        if (t < IN_F) {
            us[t] = ((const float4*)W_or_us)[t];
            ud[t] = ((const float4*)u_dst)[t];
        }
    }
    __syncthreads();
    int n    = (blockIdx.x * blockDim.x + t) >> 5;
    int lane = t & 31;
    if (n >= N) return;
    float4 xx = ((const float4*)(x + (size_t)n * IN_F))[lane];
    float4 s = make_float4(0.f, 0.f, 0.f, 0.f);
    float4 d = make_float4(0.f, 0.f, 0.f, 0.f);
    int kb = lane * 4;
    float xv[4] = {xx.x, xx.y, xx.z, xx.w};
#pragma unroll
    for (int i = 0; i < 4; i++) {
        float4 uu = us[kb + i];
        s.x += xv[i] * uu.x; s.y += xv[i] * uu.y; s.z += xv[i] * uu.z; s.w += xv[i] * uu.w;
        float4 vv = ud[kb + i];
        d.x += xv[i] * vv.x; d.y += xv[i] * vv.y; d.z += xv[i] * vv.z; d.w += xv[i] * vv.w;
    }
#pragma unroll
    for (int o = 16; o; o >>= 1) {
        s.x += __shfl_xor_sync(0xffffffffu, s.x, o);
        s.y += __shfl_xor_sync(0xffffffffu, s.y, o);
        s.z += __shfl_xor_sync(0xffffffffu, s.z, o);
        s.w += __shfl_xor_sync(0xffffffffu, s.w, o);
        d.x += __shfl_xor_sync(0xffffffffu, d.x, o);
        d.y += __shfl_xor_sync(0xffffffffu, d.y, o);
        d.z += __shfl_xor_sync(0xffffffffu, d.z, o);
        d.w += __shfl_xor_sync(0xffffffffu, d.w, o);
    }
    if (lane == 0) {
        as4[n] = s;
        ad4[n] = d;
    }
}

// ============ fused gather, 4 heads, fp16 h: warp per node ===================
template<typename OutT>
__global__ __launch_bounds__(256) void gat_gather_h4h(
        const int* __restrict__ rowptr, const int* __restrict__ colv,
        const float4* __restrict__ as4, const float4* __restrict__ ad4,
        const __half* __restrict__ h, const float* __restrict__ bias,
        OutT* __restrict__ outbuf, float4* __restrict__ ealpha, int N) {
    __shared__ float4 sal[8][32];
    __shared__ int    ssrc[8][32];
    int wid  = threadIdx.x >> 5;
    int lane = threadIdx.x & 31;
    int n    = (blockIdx.x * blockDim.x + threadIdx.x) >> 5;
    if (n >= N) return;
    int start = rowptr[n], end = rowptr[n + 1];
    bool small = (end - start) <= 32;
    float4 adv = ad4[n];

    float4 ssum = make_float4(0.f, 0.f, 0.f, 0.f);
    float4 myal = make_float4(0.f, 0.f, 0.f, 0.f);
    for (int j = start + lane; j < end; j += 32) {
        float4 v = as4[colv[j]];
        v.x += adv.x; v.y += adv.y; v.z += adv.z; v.w += adv.w;
        v.x = (v.x > 0.f) ? v.x : 0.2f * v.x;
        v.y = (v.y > 0.f) ? v.y : 0.2f * v.y;
        v.z = (v.z > 0.f) ? v.z : 0.2f * v.z;
        v.w = (v.w > 0.f) ? v.w : 0.2f * v.w;
        v.x = __expf(v.x); v.y = __expf(v.y); v.z = __expf(v.z); v.w = __expf(v.w);
        if (!small) ealpha[j] = v;
        myal = v;
        ssum.x += v.x; ssum.y += v.y; ssum.z += v.z; ssum.w += v.w;
    }
#pragma unroll
    for (int o = 16; o; o >>= 1) {
        ssum.x += __shfl_xor_sync(0xffffffffu, ssum.x, o);
        ssum.y += __shfl_xor_sync(0xffffffffu, ssum.y, o);
        ssum.z += __shfl_xor_sync(0xffffffffu, ssum.z, o);
        ssum.w += __shfl_xor_sync(0xffffffffu, ssum.w, o);
    }
    float4 inv = make_float4(1.f / (ssum.x + 1e-16f), 1.f / (ssum.y + 1e-16f),
                             1.f / (ssum.z + 1e-16f), 1.f / (ssum.w + 1e-16f));

    const int hd = lane >> 3;
    float acc[8] = {};
    for (int base = start; base < end; base += 32) {
        int jj = base + lane;
        if (jj < end) {
            ssrc[wid][lane] = colv[jj];
            sal[wid][lane]  = small ? myal : ealpha[jj];
        }
        __syncwarp();
        int kmax = min(32, end - base);
        for (int k = 0; k < kmax; k++) {
            int   s_k = ssrc[wid][k];
            float aA  = ((const float*)&sal[wid][k])[hd];
            float4 raw = ((const float4*)(h + (size_t)s_k * 256))[lane];
            const __half2* hh = (const __half2*)&raw;
#pragma unroll
            for (int i = 0; i < 4; i++) {
                float2 f = __half22float2(hh[i]);
                acc[2 * i]     += aA * f.x;
                acc[2 * i + 1] += aA * f.y;
            }
        }
        __syncwarp();
    }

    float invA = (hd == 0) ? inv.x : (hd == 1) ? inv.y : (hd == 2) ? inv.z : inv.w;
    float4 b0 = ((const float4*)bias)[2 * lane];
    float4 b1 = ((const float4*)bias)[2 * lane + 1];
    float o0 = fmaxf(acc[0] * invA + b0.x, 0.f), o1 = fmaxf(acc[1] * invA + b0.y, 0.f);
    float o2 = fmaxf(acc[2] * invA + b0.z, 0.f), o3 = fmaxf(acc[3] * invA + b0.w, 0.f);
    float o4v = fmaxf(acc[4] * invA + b1.x, 0.f), o5 = fmaxf(acc[5] * invA + b1.y, 0.f);
    float o6 = fmaxf(acc[6] * invA + b1.z, 0.f), o7 = fmaxf(acc[7] * invA + b1.w, 0.f);
    if constexpr (sizeof(OutT) == 2) {
        __half2 p[4] = {__floats2half2_rn(o0, o1), __floats2half2_rn(o2, o3),
                        __floats2half2_rn(o4v, o5), __floats2half2_rn(o6, o7)};
        *(uint4*)(outbuf + (size_t)n * 256 + lane * 8) = *(const uint4*)p;
    } else {
        float4* o4p = (float4*)((float*)outbuf + (size_t)n * 256);
        o4p[2 * lane]     = make_float4(o0, o1, o2, o3);
        o4p[2 * lane + 1] = make_float4(o4v, o5, o6, o7);
    }
}

// ============ fused gather, 1 head: warp per node ============================
template<typename HT, int C, int ACT>
__global__ void gat_gather1(const int* __restrict__ rowptr, const int* __restrict__ colv,
                            const float* __restrict__ as_, const float* __restrict__ ad_,
                            const HT* __restrict__ h, const float* __restrict__ bias,
                            float* __restrict__ outbuf, float* __restrict__ ealpha, int N) {
    int n    = (blockIdx.x * blockDim.x + threadIdx.x) >> 5;
    int lane = threadIdx.x & 31;
    if (n >= N) return;
    int start = rowptr[n], end = rowptr[n + 1];
    bool small = (end - start) <= 32;
    float adv = ad_[n];

    float ssum = 0.f, myal = 0.f;
    for (int j = start + lane; j < end; j += 32) {
        float v = as_[colv[j]] + adv;
        v = (v > 0.f) ? v : 0.2f * v;
        v = __expf(v);
        if (!small) ealpha[j] = v;
        myal = v;
        ssum += v;
    }
#pragma unroll
    for (int o = 16; o; o >>= 1) ssum += __shfl_xor_sync(0xffffffffu, ssum, o);
    float inv = 1.f / (ssum + 1e-16f);

    float acc0 = 0.f, acc1 = 0.f;
    for (int base = start; base < end; base += 32) {
        int jj = base + lane;
        int srcv = 0; float al = 0.f;
        if (jj < end) {
            srcv = colv[jj];
            al = small ? myal : ealpha[jj];
        }
        int kmax = min(32, end - base);
        for (int k = 0; k < kmax; k++) {
            int   s_k = __shfl_sync(0xffffffffu, srcv, k);
            float a_k = __shfl_sync(0xffffffffu, al,   k);
            const HT* hp = h + (size_t)s_k * C;
            acc0 += a_k * to_f(hp[lane]);
            if (C == 64) acc1 += a_k * to_f(hp[lane + 32]);
        }
    }

    if (ACT == 2) {
        float v = acc0 * inv + bias[lane];
        float m = v;
#pragma unroll
        for (int o = 16; o; o >>= 1) m = fmaxf(m, __shfl_xor_sync(0xffffffffu, m, o));
        float ex = __expf(v - m);
        float se = ex;
#pragma unroll
        for (int o = 16; o; o >>= 1) se += __shfl_xor_sync(0xffffffffu, se, o);
        outbuf[(size_t)n * 32 + lane] = (v - m) - logf(se);
    } else {
        outbuf[(size_t)n * C + lane] = acc0 * inv + bias[lane];
        if (C == 64)
            outbuf[(size_t)n * C + lane + 32] = acc1 * inv + bias[lane + 32];
    }
}

// --------------------------------- host side --------------------------------
template<typename T>
static inline T* sym(const void* s) {
    void* p = nullptr;
    cudaGetSymbolAddress(&p, s);
    return (T*)p;
}

extern "C" void kernel_launch(void* const* d_in, const int* in_sizes, int n_in,
                              void* d_out, int out_size) {
    const float* dept_x  = (const float*)d_in[0];
    const int*   dept_ei = (const int*)  d_in[1];
    const float* emp_x   = (const float*)d_in[2];
    const int*   emp_ei  = (const int*)  d_in[3];
    const int*   dept_ix = (const int*)  d_in[4];
    const float* W_d1    = (const float*)d_in[5];
    const float* as_d1   = (const float*)d_in[6];
    const float* ad_d1   = (const float*)d_in[7];
    const float* b_d1    = (const float*)d_in[8];
    const float* W_d2    = (const float*)d_in[9];
    const float* as_d2   = (const float*)d_in[10];
    const float* ad_d2   = (const float*)d_in[11];
    const float* b_d2    = (const float*)d_in[12];
    const float* W_e1    = (const float*)d_in[13];
    const float* as_e1   = (const float*)d_in[14];
    const float* ad_e1   = (const float*)d_in[15];
    const float* b_e1    = (const float*)d_in[16];
    const float* W_e2    = (const float*)d_in[17];
    const float* as_e2   = (const float*)d_in[18];
    const float* ad_e2   = (const float*)d_in[19];
    const float* b_e2    = (const float*)d_in[20];
    float* out = (float*)d_out;

    static cudaStream_t side = nullptr, side2 = nullptr;
    static cudaEvent_t evF = nullptr, evC = nullptr, evV = nullptr;
    if (!side) {
        cudaStreamCreateWithFlags(&side, cudaStreamNonBlocking);
        cudaStreamCreateWithFlags(&side2, cudaStreamNonBlocking);
        cudaEventCreateWithFlags(&evF, cudaEventDisableTiming);
        cudaEventCreateWithFlags(&evC, cudaEventDisableTiming);
        cudaEventCreateWithFlags(&evV, cudaEventDisableTiming);
    }

    __half *p_d_h1h = sym<__half>(g_d_h1h), *p_e_h1h = sym<__half>(g_e_h1h);
    __half *p_e_out1h = sym<__half>(g_e_out1h), *p_e_h2h = sym<__half>(g_e_h2h);
    float *p_d_as1 = sym<float>(g_d_as1), *p_d_ad1 = sym<float>(g_d_ad1);
    float *p_d_out1 = sym<float>(g_d_out1), *p_d_h2 = sym<float>(g_d_h2);
    float *p_d_as2 = sym<float>(g_d_as2), *p_d_ad2 = sym<float>(g_d_ad2), *p_d_out2 = sym<float>(g_d_out2);
    float *p_dproj = sym<float>(g_dproj);
    float *p_e_as1 = sym<float>(g_e_as1), *p_e_ad1 = sym<float>(g_e_ad1);
    float *p_e_as2 = sym<float>(g_e_as2), *p_e_ad2 = sym<float>(g_e_ad2);
    float *p_usrc = sym<float>(g_u_src), *p_udst = sym<float>(g_u_dst);
    float *p_vsrc = sym<float>(g_v_src), *p_vdst = sym<float>(g_v_dst);
    float4 *p_ealpha = sym<float4>(g_ealpha);

    int *deg_d = sym<int>(g_deg_d), *cur_d = sym<int>(g_cur_d), *row_d = sym<int>(g_row_d);
    int *col_d = sym<int>(g_colv_d);
    int *degcur_e = sym<int>(g_degcur_e);
    int *deg_e = degcur_e, *cur_e = degcur_e + N_E;
    int *row_e = sym<int>(g_row_e), *col_e = sym<int>(g_colv_e), *bs_e = sym<int>(g_bs_e);

    const int TB = 256;

    // ---- fork ----
    cudaEventRecord(evF, 0);
    cudaStreamWaitEvent(side, evF, 0);
    cudaStreamWaitEvent(side2, evF, 0);

    // side2: dept CSR build (concurrent with dept1 GEMM)
    build_csr_small<<<1, 1024, 0, side2>>>(dept_ei, E_D, N_D, deg_d, cur_d, row_d, col_d);
    cudaEventRecord(evC, side2);

    // side: dept compute chain
    {
        dim3 g(cdiv(HEADS * DHC, 128), cdiv(N_D, 128));
        gemm_tc<__half><<<g, 256, 0, side>>>(dept_x, W_d1, p_d_h1h, N_D, HEADS * DHC, IN_F, nullptr, nullptr);
    }
    node_alpha<true><<<cdiv(N_D * 32, TB), TB, 0, side>>>(
        dept_x, W_d1, nullptr, as_d1, ad_d1, (float4*)p_d_as1, (float4*)p_d_ad1, N_D);
    cudaStreamWaitEvent(side, evC, 0);
    gat_gather_h4h<float><<<cdiv(N_D * 32, TB), TB, 0, side>>>(
        row_d, col_d, (const float4*)p_d_as1, (const float4*)p_d_ad1,
        p_d_h1h, b_d1, p_d_out1, p_ealpha, N_D);
    {
        dim3 g(1, cdiv(N_D, 64));
        gemm64a<<<g, 256, 0, side>>>(p_d_out1, W_d2, p_d_h2, N_D, DHC, HEADS * DHC,
                                     as_d2, ad_d2, p_d_as2, p_d_ad2);
    }
    gat_gather1<float, DHC, 0><<<cdiv(N_D * 32, TB), TB, 0, side>>>(
        row_d, col_d, p_d_as2, p_d_ad2, p_d_h2, b_d2, p_d_out2, (float*)p_ealpha, N_D);
    {
        dim3 g(cdiv(HEADS * EHC, 128), cdiv(N_D, 128));
        gemm_tc<float><<<g, 256, 0, side>>>(p_d_out2, W_e1 + (size_t)IN_F * HEADS * EHC, p_dproj,
                                            N_D, HEADS * EHC, DHC, nullptr, nullptr);
    }
    compute_v<<<cdiv(N_D * HEADS, 256), 256, 0, side>>>(p_dproj, as_e1, ad_e1, p_vsrc, p_vdst);
    cudaEventRecord(evV, side);

    // main: emp CSR build + u precompute + emp alpha partial — overlaps dept chain
    cudaMemsetAsync(degcur_e, 0, sizeof(int) * 2 * N_E);
    compute_u<<<1, 128>>>(W_e1, as_e1, ad_e1, p_usrc, p_udst);
    {
        int nb = cdiv(N_E, 256);
        deg_count<<<cdiv(E_E, TB), TB>>>(emp_ei, E_E, deg_e);
        block_sum<<<nb, 256>>>(deg_e, N_E, bs_e);
        scan_bsums<<<1, 32>>>(bs_e, nb, row_e, E_E + N_E, N_E);
        scan_final<<<nb, 256>>>(deg_e, bs_e, N_E, row_e);
        fill_csr<<<cdiv(E_E + N_E, TB), TB>>>(emp_ei, E_E, N_E, row_e, cur_e, col_e);
    }
    node_alpha<false><<<cdiv(N_E * 32, TB), TB>>>(
        emp_x, p_usrc, p_udst, nullptr, nullptr, (float4*)p_e_as1, (float4*)p_e_ad1, N_E);

    // ---- join: main waits for side's dproj + v ----
    cudaStreamWaitEvent(0, evV, 0);

    // emp1 GEMM depends only on dproj — launch FIRST so vadd overlaps its ramp
    {
        dim3 g(cdiv(HEADS * EHC, 128), cdiv(N_E, 128));
        gemm_tc<__half><<<g, 256>>>(emp_x, W_e1, p_e_h1h, N_E, HEADS * EHC, IN_F, p_dproj, dept_ix);
    }
    vadd_alpha<<<cdiv(N_E, TB), TB>>>(dept_ix, p_vsrc, p_vdst,
                                      (float4*)p_e_as1, (float4*)p_e_ad1, N_E);
    gat_gather_h4h<__half><<<cdiv(N_E * 32, TB), TB>>>(
        row_e, col_e, (const float4*)p_e_as1, (const float4*)p_e_ad1,
        p_e_h1h, b_e1, p_e_out1h, p_ealpha, N_E);

    // ============ emp layer 2: fp16 HMMA GEMM + fused alpha + log_softmax ====
    gemm_n32_h<<<cdiv(N_E, 128), 256>>>(p_e_out1h, W_e2, p_e_h2h, N_E, HEADS * EHC,
                                        as_e2, ad_e2, p_e_as2, p_e_ad2);
    gat_gather1<__half, OUTC, 2><<<cdiv(N_E * 32, TB), TB>>>(
        row_e, col_e, p_e_as2, p_e_ad2, p_e_h2h, b_e2, out, (float*)p_ealpha, N_E);
}